// round 16
// baseline (speedup 1.0000x reference)
#include <cuda_runtime.h>

#define BB 32
#define SS 2048
#define DD 1024
#define KATT 10
#define CHUNKS 32
#define ROWS_PER_CHUNK (SS / CHUNKS)   // 64
#define D4 (DD / 4)                    // 256 float4 per row
#define RETAIN_ROWS 24                 // rows 0..23 of each chunk kept in L2 (96 MB)
#define PF_BLOCKS 112                  // kmid prefetch blocks (~17.5 MB)

// Scratch (no allocation allowed)
__device__ float g_partial[BB * CHUNKS * DD];  // 4 MB
__device__ float g_vraw[BB * DD];
__device__ float g_corr[BB * DD];
__device__ float g_s1[KATT];    // 1/max(|a|,1e-8)
__device__ float g_cs[KATT];    // cosine scale: s1 / max(|a|*s1, 1e-12)

// kmid barrier state (self-resetting per launch; graph-replay safe)
__device__ int g_cnt = 0;
__device__ volatile unsigned g_gen = 0;

// ---------------------------------------------------------------------------
// k1: blocks 0..1023 -> partial sums over sequence chunks (block = b*32+c,
//     sums 64 rows). Blocks 1024..1033 -> attractor norm scales (block per k).
// Cache policy: rows 24..63 evict-first (__ldcs, read-once) FIRST, then rows
// 0..23 NORMAL (__ldcg) LAST -> ~96 MB stays L2-resident, youngest at exit,
// matching what k3's earliest blocks read.
// ---------------------------------------------------------------------------
__global__ void __launch_bounds__(256) k1_partial(const float* __restrict__ h,
                                                  const float* __restrict__ att) {
    if (blockIdx.x < BB * CHUNKS) {
        const float4* h4 = (const float4*)h;
        const float4* p = h4 + ((size_t)blockIdx.x << 14) + threadIdx.x; // 64*256 f4/block
        float4 acc = make_float4(0.f, 0.f, 0.f, 0.f);
#pragma unroll 8
        for (int s = RETAIN_ROWS; s < ROWS_PER_CHUNK; ++s) {
            float4 v = __ldcs(&p[s * D4]);               // read-once: evict-first
            acc.x += v.x; acc.y += v.y; acc.z += v.z; acc.w += v.w;
        }
#pragma unroll 8
        for (int s = 0; s < RETAIN_ROWS; ++s) {
            float4 v = __ldcg(&p[s * D4]);               // retain in L2 for k3
            acc.x += v.x; acc.y += v.y; acc.z += v.z; acc.w += v.w;
        }
        ((float4*)g_partial)[blockIdx.x * D4 + threadIdx.x] = acc;
        cudaTriggerProgrammaticLaunchCompletion();
    } else {
        // attractor scales: one block per k, 256 threads, 1 float4 each
        int k = blockIdx.x - BB * CHUNKS;
        int t = threadIdx.x;
        __shared__ float s_part[8];
        float4 a = ((const float4*)att)[k * D4 + t];
        float p = a.x * a.x + a.y * a.y + a.z * a.z + a.w * a.w;
#pragma unroll
        for (int o = 16; o; o >>= 1) p += __shfl_xor_sync(0xffffffff, p, o);
        if ((t & 31) == 0) s_part[t >> 5] = p;
        __syncthreads();
        if (t == 0) {
            float s = 0.f;
#pragma unroll
            for (int w = 0; w < 8; ++w) s += s_part[w];
            float n1 = sqrtf(s);
            float s1 = 1.0f / fmaxf(n1, 1e-8f);
            float n2 = n1 * s1;
            g_s1[k] = s1;
            g_cs[k] = s1 / fmaxf(n2, 1e-12f);
        }
        __syncthreads();
        cudaTriggerProgrammaticLaunchCompletion();
    }
}

// ---------------------------------------------------------------------------
// kmid: fused k1b + whitening + snap (blocks 0..31) plus L2 prefetch of k3's
// earliest non-retained reads (blocks 32..143). Triggers launch completion at
// entry so k3 launches immediately; gridsync waits for k1's partials.
// ---------------------------------------------------------------------------
__global__ void __launch_bounds__(256) kmid(const float* __restrict__ h,
                                            const float* __restrict__ att) {
    cudaTriggerProgrammaticLaunchCompletion();   // let k3 launch now
    cudaGridDependencySynchronize();             // wait for k1 results

    // ---- prefetch-only blocks: rows 24..63 of chunk (x-32), 160 KB each ----
    if (blockIdx.x >= BB) {
        int px = blockIdx.x - BB;                         // 0..111 -> chunk px
        const char* base = (const char*)h
            + (size_t)px * (ROWS_PER_CHUNK * DD * 4)      // 256 KB per chunk
            + (size_t)RETAIN_ROWS * DD * 4;               // skip retained 96 KB
        // (64-24)*4 KB = 160 KB = 1280 lines; 256 threads x 5 lines
#pragma unroll
        for (int i = 0; i < 5; ++i) {
            const char* a = base + (size_t)threadIdx.x * 128 + (size_t)i * 32768;
            asm volatile("prefetch.global.L2 [%0];" :: "l"(a));
        }
        return;
    }

    __shared__ float s_part[KATT][8];
    __shared__ float s_cs[KATT];
    __shared__ float s_s1[KATT];
    __shared__ unsigned s_gen;

    const int b = blockIdx.x;
    const int t = threadIdx.x;
    const int lane = t & 31;
    const int wid = t >> 5;
    const float4* gp4 = (const float4*)g_partial;
    float4* vr4 = (float4*)g_vraw;
    const float4* at4 = (const float4*)att;

    if (t == 0) s_gen = g_gen;
    if (t >= 32 && t < 32 + KATT) s_cs[t - 32] = g_cs[t - 32];
    if (t >= 64 && t < 64 + KATT) s_s1[t - 64] = g_s1[t - 64];

    // --- 1. reduce partials -> vraw[b] ---
    float4 acc = make_float4(0.f, 0.f, 0.f, 0.f);
#pragma unroll
    for (int c = 0; c < CHUNKS; ++c) {
        float4 v = gp4[(b * CHUNKS + c) * D4 + t];
        acc.x += v.x; acc.y += v.y; acc.z += v.z; acc.w += v.w;
    }
    {
        const float inv = 1.0f / (float)SS;
        acc.x *= inv; acc.y *= inv; acc.z *= inv; acc.w *= inv;
    }
    vr4[b * D4 + t] = acc;

    // --- 2. grid barrier over the 32 math blocks ---
    __syncthreads();
    if (t == 0) {
        __threadfence();
        int a = atomicAdd(&g_cnt, 1);
        if (a == BB - 1) {
            g_cnt = 0;
            __threadfence();
            g_gen = s_gen + 1;
        }
        while (g_gen == s_gen) { }
    }
    __syncthreads();
    __threadfence();

    // --- 3. whitening stats (identical fixed-order in every block) ---
    float4 sum = make_float4(0.f, 0.f, 0.f, 0.f);
    float4 sq = make_float4(0.f, 0.f, 0.f, 0.f);
#pragma unroll
    for (int bb = 0; bb < BB; ++bb) {
        float4 v = vr4[bb * D4 + t];
        sum.x += v.x; sum.y += v.y; sum.z += v.z; sum.w += v.w;
        sq.x += v.x * v.x; sq.y += v.y * v.y; sq.z += v.z * v.z; sq.w += v.w * v.w;
    }
    const float invB = 1.0f / (float)BB;
    float4 mean = make_float4(sum.x * invB, sum.y * invB, sum.z * invB, sum.w * invB);
    float4 inv;
    inv.x = 1.0f / sqrtf(sq.x * invB - mean.x * mean.x + 1e-8f);
    inv.y = 1.0f / sqrtf(sq.y * invB - mean.y * mean.y + 1e-8f);
    inv.z = 1.0f / sqrtf(sq.z * invB - mean.z * mean.z + 1e-8f);
    inv.w = 1.0f / sqrtf(sq.w * invB - mean.w * mean.w + 1e-8f);
    float4 vn;
    vn.x = (acc.x - mean.x) * inv.x;
    vn.y = (acc.y - mean.y) * inv.y;
    vn.z = (acc.z - mean.z) * inv.z;
    vn.w = (acc.w - mean.w) * inv.w;

    // --- 4. cosines: partial dots, 10 shfl trees, one sync, uniform argmax ---
    float p[KATT];
#pragma unroll
    for (int k = 0; k < KATT; ++k) {
        float4 a = at4[k * D4 + t];
        p[k] = vn.x * a.x + vn.y * a.y + vn.z * a.z + vn.w * a.w;
    }
#pragma unroll
    for (int k = 0; k < KATT; ++k) {
#pragma unroll
        for (int o = 16; o; o >>= 1) p[k] += __shfl_xor_sync(0xffffffff, p[k], o);
        if (lane == 0) s_part[k][wid] = p[k];
    }
    __syncthreads();

    float best = -1e30f;
    int bi = 0;
#pragma unroll
    for (int k = 0; k < KATT; ++k) {
        float dot = 0.f;
#pragma unroll
        for (int w = 0; w < 8; ++w) dot += s_part[k][w];   // fixed order: deterministic
        float cosv = dot * s_cs[k];
        if (cosv > best) { best = cosv; bi = k; }          // strict > == jnp first-max
    }

    // --- 5. correction = v_norm + alpha*clip(closest - v_norm) - v_raw ---
    {
        float s1 = s_s1[bi];
        float al = 0.3f * (1.0f - best);
        float4 a = at4[bi * D4 + t];
        float4 o;
        float dx = fminf(fmaxf(a.x * s1 - vn.x, -0.5f), 0.5f);
        float dy = fminf(fmaxf(a.y * s1 - vn.y, -0.5f), 0.5f);
        float dz = fminf(fmaxf(a.z * s1 - vn.z, -0.5f), 0.5f);
        float dw = fminf(fmaxf(a.w * s1 - vn.w, -0.5f), 0.5f);
        o.x = vn.x + al * dx - acc.x;
        o.y = vn.y + al * dy - acc.y;
        o.z = vn.z + al * dz - acc.z;
        o.w = vn.w + al * dw - acc.w;
        ((float4*)g_corr)[b * D4 + t] = o;
    }
}

// ---------------------------------------------------------------------------
// k3: out = h + corr broadcast, 8 float4 per thread, PDL-launched.
// h loads issued BEFORE the grid-dependency sync (hide kmid); __ldcs reads hit
// the retained/prefetched L2 set and demote after use; __stcs write-back
// stores (measured best: wt regressed 3.2us in R15).
// ---------------------------------------------------------------------------
__global__ void __launch_bounds__(256) k3_apply(const float* __restrict__ h,
                                                float* __restrict__ out) {
    const float4* h4 = (const float4*)h;
    float4* o4 = (float4*)out;
    unsigned base = blockIdx.x * 2048u + threadIdx.x;
    float4 v0 = __ldcs(&h4[base]);
    float4 v1 = __ldcs(&h4[base + 256]);
    float4 v2 = __ldcs(&h4[base + 512]);
    float4 v3 = __ldcs(&h4[base + 768]);
    float4 v4 = __ldcs(&h4[base + 1024]);
    float4 v5 = __ldcs(&h4[base + 1280]);
    float4 v6 = __ldcs(&h4[base + 1536]);
    float4 v7 = __ldcs(&h4[base + 1792]);
    cudaGridDependencySynchronize();         // wait for kmid's corr
    unsigned b = base >> 19;                 // uniform per block
    float4 c = ((const float4*)g_corr)[(b << 8) + threadIdx.x];
    v0.x += c.x; v0.y += c.y; v0.z += c.z; v0.w += c.w;
    v1.x += c.x; v1.y += c.y; v1.z += c.z; v1.w += c.w;
    v2.x += c.x; v2.y += c.y; v2.z += c.z; v2.w += c.w;
    v3.x += c.x; v3.y += c.y; v3.z += c.z; v3.w += c.w;
    v4.x += c.x; v4.y += c.y; v4.z += c.z; v4.w += c.w;
    v5.x += c.x; v5.y += c.y; v5.z += c.z; v5.w += c.w;
    v6.x += c.x; v6.y += c.y; v6.z += c.z; v6.w += c.w;
    v7.x += c.x; v7.y += c.y; v7.z += c.z; v7.w += c.w;
    __stcs(&o4[base], v0);
    __stcs(&o4[base + 256], v1);
    __stcs(&o4[base + 512], v2);
    __stcs(&o4[base + 768], v3);
    __stcs(&o4[base + 1024], v4);
    __stcs(&o4[base + 1280], v5);
    __stcs(&o4[base + 1536], v6);
    __stcs(&o4[base + 1792], v7);
}

// ---------------------------------------------------------------------------
extern "C" void kernel_launch(void* const* d_in, const int* in_sizes, int n_in,
                              void* d_out, int out_size) {
    const float* hidden = (const float*)d_in[0];   // [32, 2048, 1024] f32
    const float* att    = (const float*)d_in[1];   // [10, 1024] f32
    float* out = (float*)d_out;

    k1_partial<<<BB * CHUNKS + KATT, 256>>>(hidden, att);

    cudaLaunchAttribute attrs[1];
    attrs[0].id = cudaLaunchAttributeProgrammaticStreamSerialization;
    attrs[0].val.programmaticStreamSerializationAllowed = 1;

    {   // kmid with PDL (overlaps k1 tail)
        cudaLaunchConfig_t cfg = {};
        cfg.gridDim = dim3(BB + PF_BLOCKS, 1, 1);
        cfg.blockDim = dim3(256, 1, 1);
        cfg.stream = 0;
        cfg.attrs = attrs;
        cfg.numAttrs = 1;
        cudaLaunchKernelEx(&cfg, kmid, hidden, att);
    }
    {   // k3 with PDL (launches during kmid; loads issued before gridsync)
        const unsigned total4 = (unsigned)BB * SS * D4;   // 16,777,216 float4
        cudaLaunchConfig_t cfg = {};
        cfg.gridDim = dim3(total4 / 2048, 1, 1);          // 8192 blocks
        cfg.blockDim = dim3(256, 1, 1);
        cfg.stream = 0;
        cfg.attrs = attrs;
        cfg.numAttrs = 1;
        cudaLaunchKernelEx(&cfg, k3_apply, hidden, out);
    }
}

// round 17
// speedup vs baseline: 1.0656x; 1.0656x over previous
#include <cuda_runtime.h>

#define BB 32
#define SS 2048
#define DD 1024
#define KATT 10
#define CHUNKS 32
#define ROWS_PER_CHUNK (SS / CHUNKS)   // 64
#define D4 (DD / 4)                    // 256 float4 per row
#define RETAIN_ROWS 24                 // rows 0..23 of each chunk kept in L2 (96 MB)

// Scratch (no allocation allowed)
__device__ float g_partial[BB * CHUNKS * DD];  // 4 MB
__device__ float g_vraw[BB * DD];
__device__ float g_corr[BB * DD];
__device__ float g_s1[KATT];    // 1/max(|a|,1e-8)
__device__ float g_cs[KATT];    // cosine scale: s1 / max(|a|*s1, 1e-12)

// kmid barrier state (self-resetting per launch; graph-replay safe)
__device__ int g_cnt = 0;
__device__ volatile unsigned g_gen = 0;

// ---------------------------------------------------------------------------
// k1: blocks 0..1023 -> partial sums over sequence chunks (block = b*32+c,
//     sums 64 rows). Blocks 1024..1033 -> attractor norm scales (block per k).
// Cache policy: rows 24..63 evict-first (__ldcs, read-once) FIRST, then rows
// 0..23 NORMAL (__ldcg) LAST -> ~96 MB stays L2-resident, youngest at exit,
// matching what k3's earliest blocks read.
// ---------------------------------------------------------------------------
__global__ void __launch_bounds__(256) k1_partial(const float* __restrict__ h,
                                                  const float* __restrict__ att) {
    if (blockIdx.x < BB * CHUNKS) {
        const float4* h4 = (const float4*)h;
        const float4* p = h4 + ((size_t)blockIdx.x << 14) + threadIdx.x; // 64*256 f4/block
        float4 acc = make_float4(0.f, 0.f, 0.f, 0.f);
#pragma unroll 8
        for (int s = RETAIN_ROWS; s < ROWS_PER_CHUNK; ++s) {
            float4 v = __ldcs(&p[s * D4]);               // read-once: evict-first
            acc.x += v.x; acc.y += v.y; acc.z += v.z; acc.w += v.w;
        }
#pragma unroll 8
        for (int s = 0; s < RETAIN_ROWS; ++s) {
            float4 v = __ldcg(&p[s * D4]);               // retain in L2 for k3
            acc.x += v.x; acc.y += v.y; acc.z += v.z; acc.w += v.w;
        }
        ((float4*)g_partial)[blockIdx.x * D4 + threadIdx.x] = acc;
        cudaTriggerProgrammaticLaunchCompletion();
    } else {
        // attractor scales: one block per k, 256 threads, 1 float4 each
        int k = blockIdx.x - BB * CHUNKS;
        int t = threadIdx.x;
        __shared__ float s_part[8];
        float4 a = ((const float4*)att)[k * D4 + t];
        float p = a.x * a.x + a.y * a.y + a.z * a.z + a.w * a.w;
#pragma unroll
        for (int o = 16; o; o >>= 1) p += __shfl_xor_sync(0xffffffff, p, o);
        if ((t & 31) == 0) s_part[t >> 5] = p;
        __syncthreads();
        if (t == 0) {
            float s = 0.f;
#pragma unroll
            for (int w = 0; w < 8; ++w) s += s_part[w];
            float n1 = sqrtf(s);
            float s1 = 1.0f / fmaxf(n1, 1e-8f);
            float n2 = n1 * s1;
            g_s1[k] = s1;
            g_cs[k] = s1 / fmaxf(n2, 1e-12f);
        }
        __syncthreads();
        cudaTriggerProgrammaticLaunchCompletion();
    }
}

// ---------------------------------------------------------------------------
// kmid: fused k1b + whitening + snap. 32 blocks (one per batch row) x 256 thr.
// NO prefetch blocks: under PDL, k3's own wave-1 loads are already in flight
// during kmid — prefetch only contended with them (R16: regression).
// Triggers launch completion at entry so k3 launches immediately; gridsync
// waits for k1's partials.
// ---------------------------------------------------------------------------
__global__ void __launch_bounds__(256) kmid(const float* __restrict__ att) {
    cudaTriggerProgrammaticLaunchCompletion();   // let k3 launch now
    cudaGridDependencySynchronize();             // wait for k1 results

    __shared__ float s_part[KATT][8];
    __shared__ float s_cs[KATT];
    __shared__ float s_s1[KATT];
    __shared__ unsigned s_gen;

    const int b = blockIdx.x;
    const int t = threadIdx.x;
    const int lane = t & 31;
    const int wid = t >> 5;
    const float4* gp4 = (const float4*)g_partial;
    float4* vr4 = (float4*)g_vraw;
    const float4* at4 = (const float4*)att;

    if (t == 0) s_gen = g_gen;
    if (t >= 32 && t < 32 + KATT) s_cs[t - 32] = g_cs[t - 32];
    if (t >= 64 && t < 64 + KATT) s_s1[t - 64] = g_s1[t - 64];

    // --- 1. reduce partials -> vraw[b] ---
    float4 acc = make_float4(0.f, 0.f, 0.f, 0.f);
#pragma unroll
    for (int c = 0; c < CHUNKS; ++c) {
        float4 v = gp4[(b * CHUNKS + c) * D4 + t];
        acc.x += v.x; acc.y += v.y; acc.z += v.z; acc.w += v.w;
    }
    {
        const float inv = 1.0f / (float)SS;
        acc.x *= inv; acc.y *= inv; acc.z *= inv; acc.w *= inv;
    }
    vr4[b * D4 + t] = acc;

    // --- 2. grid barrier over the 32 math blocks ---
    __syncthreads();
    if (t == 0) {
        __threadfence();
        int a = atomicAdd(&g_cnt, 1);
        if (a == BB - 1) {
            g_cnt = 0;
            __threadfence();
            g_gen = s_gen + 1;
        }
        while (g_gen == s_gen) { }
    }
    __syncthreads();
    __threadfence();

    // --- 3. whitening stats (identical fixed-order in every block) ---
    float4 sum = make_float4(0.f, 0.f, 0.f, 0.f);
    float4 sq = make_float4(0.f, 0.f, 0.f, 0.f);
#pragma unroll
    for (int bb = 0; bb < BB; ++bb) {
        float4 v = vr4[bb * D4 + t];
        sum.x += v.x; sum.y += v.y; sum.z += v.z; sum.w += v.w;
        sq.x += v.x * v.x; sq.y += v.y * v.y; sq.z += v.z * v.z; sq.w += v.w * v.w;
    }
    const float invB = 1.0f / (float)BB;
    float4 mean = make_float4(sum.x * invB, sum.y * invB, sum.z * invB, sum.w * invB);
    float4 inv;
    inv.x = 1.0f / sqrtf(sq.x * invB - mean.x * mean.x + 1e-8f);
    inv.y = 1.0f / sqrtf(sq.y * invB - mean.y * mean.y + 1e-8f);
    inv.z = 1.0f / sqrtf(sq.z * invB - mean.z * mean.z + 1e-8f);
    inv.w = 1.0f / sqrtf(sq.w * invB - mean.w * mean.w + 1e-8f);
    float4 vn;
    vn.x = (acc.x - mean.x) * inv.x;
    vn.y = (acc.y - mean.y) * inv.y;
    vn.z = (acc.z - mean.z) * inv.z;
    vn.w = (acc.w - mean.w) * inv.w;

    // --- 4. cosines: partial dots, 10 shfl trees, one sync, uniform argmax ---
    float p[KATT];
#pragma unroll
    for (int k = 0; k < KATT; ++k) {
        float4 a = at4[k * D4 + t];
        p[k] = vn.x * a.x + vn.y * a.y + vn.z * a.z + vn.w * a.w;
    }
#pragma unroll
    for (int k = 0; k < KATT; ++k) {
#pragma unroll
        for (int o = 16; o; o >>= 1) p[k] += __shfl_xor_sync(0xffffffff, p[k], o);
        if (lane == 0) s_part[k][wid] = p[k];
    }
    __syncthreads();

    float best = -1e30f;
    int bi = 0;
#pragma unroll
    for (int k = 0; k < KATT; ++k) {
        float dot = 0.f;
#pragma unroll
        for (int w = 0; w < 8; ++w) dot += s_part[k][w];   // fixed order: deterministic
        float cosv = dot * s_cs[k];
        if (cosv > best) { best = cosv; bi = k; }          // strict > == jnp first-max
    }

    // --- 5. correction = v_norm + alpha*clip(closest - v_norm) - v_raw ---
    {
        float s1 = s_s1[bi];
        float al = 0.3f * (1.0f - best);
        float4 a = at4[bi * D4 + t];
        float4 o;
        float dx = fminf(fmaxf(a.x * s1 - vn.x, -0.5f), 0.5f);
        float dy = fminf(fmaxf(a.y * s1 - vn.y, -0.5f), 0.5f);
        float dz = fminf(fmaxf(a.z * s1 - vn.z, -0.5f), 0.5f);
        float dw = fminf(fmaxf(a.w * s1 - vn.w, -0.5f), 0.5f);
        o.x = vn.x + al * dx - acc.x;
        o.y = vn.y + al * dy - acc.y;
        o.z = vn.z + al * dz - acc.z;
        o.w = vn.w + al * dw - acc.w;
        ((float4*)g_corr)[b * D4 + t] = o;
    }
}

// ---------------------------------------------------------------------------
// k3: out = h + corr broadcast, 8 float4 per thread, PDL-launched.
// h loads issued BEFORE the grid-dependency sync (hide kmid); __ldcs reads hit
// the retained L2 set and demote after use; __stcs write-back stores
// (measured best: wt regressed 3.2us in R15).
// Block covers 2048 contiguous float4; 2048 | 2^19 -> b uniform per block;
// all 8 offsets == tid (mod 256) -> ONE corr load per thread.
// ---------------------------------------------------------------------------
__global__ void __launch_bounds__(256) k3_apply(const float* __restrict__ h,
                                                float* __restrict__ out) {
    const float4* h4 = (const float4*)h;
    float4* o4 = (float4*)out;
    unsigned base = blockIdx.x * 2048u + threadIdx.x;
    float4 v0 = __ldcs(&h4[base]);
    float4 v1 = __ldcs(&h4[base + 256]);
    float4 v2 = __ldcs(&h4[base + 512]);
    float4 v3 = __ldcs(&h4[base + 768]);
    float4 v4 = __ldcs(&h4[base + 1024]);
    float4 v5 = __ldcs(&h4[base + 1280]);
    float4 v6 = __ldcs(&h4[base + 1536]);
    float4 v7 = __ldcs(&h4[base + 1792]);
    cudaGridDependencySynchronize();         // wait for kmid's corr
    unsigned b = base >> 19;                 // uniform per block
    float4 c = ((const float4*)g_corr)[(b << 8) + threadIdx.x];
    v0.x += c.x; v0.y += c.y; v0.z += c.z; v0.w += c.w;
    v1.x += c.x; v1.y += c.y; v1.z += c.z; v1.w += c.w;
    v2.x += c.x; v2.y += c.y; v2.z += c.z; v2.w += c.w;
    v3.x += c.x; v3.y += c.y; v3.z += c.z; v3.w += c.w;
    v4.x += c.x; v4.y += c.y; v4.z += c.z; v4.w += c.w;
    v5.x += c.x; v5.y += c.y; v5.z += c.z; v5.w += c.w;
    v6.x += c.x; v6.y += c.y; v6.z += c.z; v6.w += c.w;
    v7.x += c.x; v7.y += c.y; v7.z += c.z; v7.w += c.w;
    __stcs(&o4[base], v0);
    __stcs(&o4[base + 256], v1);
    __stcs(&o4[base + 512], v2);
    __stcs(&o4[base + 768], v3);
    __stcs(&o4[base + 1024], v4);
    __stcs(&o4[base + 1280], v5);
    __stcs(&o4[base + 1536], v6);
    __stcs(&o4[base + 1792], v7);
}

// ---------------------------------------------------------------------------
extern "C" void kernel_launch(void* const* d_in, const int* in_sizes, int n_in,
                              void* d_out, int out_size) {
    const float* hidden = (const float*)d_in[0];   // [32, 2048, 1024] f32
    const float* att    = (const float*)d_in[1];   // [10, 1024] f32
    float* out = (float*)d_out;

    k1_partial<<<BB * CHUNKS + KATT, 256>>>(hidden, att);

    cudaLaunchAttribute attrs[1];
    attrs[0].id = cudaLaunchAttributeProgrammaticStreamSerialization;
    attrs[0].val.programmaticStreamSerializationAllowed = 1;

    {   // kmid with PDL (overlaps k1 tail)
        cudaLaunchConfig_t cfg = {};
        cfg.gridDim = dim3(BB, 1, 1);
        cfg.blockDim = dim3(256, 1, 1);
        cfg.stream = 0;
        cfg.attrs = attrs;
        cfg.numAttrs = 1;
        cudaLaunchKernelEx(&cfg, kmid, att);
    }
    {   // k3 with PDL (launches during kmid; loads issued before gridsync)
        const unsigned total4 = (unsigned)BB * SS * D4;   // 16,777,216 float4
        cudaLaunchConfig_t cfg = {};
        cfg.gridDim = dim3(total4 / 2048, 1, 1);          // 8192 blocks
        cfg.blockDim = dim3(256, 1, 1);
        cfg.stream = 0;
        cfg.attrs = attrs;
        cfg.numAttrs = 1;
        cudaLaunchKernelEx(&cfg, k3_apply, hidden, out);
    }
}